// round 2
// baseline (speedup 1.0000x reference)
#include <cuda_runtime.h>
#include <cstdint>

#define FULLMASK 0xffffffffu

// Decision of state v from ballot masks: dA bit L = decision of state (L even ? L : L+32),
// dB bit L = the complementary state. v is in the A-mask iff (v&1)==((v>>5)&1).
__device__ __forceinline__ int dec_bit(uint32_t dA, uint32_t dB, int v) {
    uint32_t m = (((v >> 5) ^ v) & 1) ? dB : dA;
    return (int)((m >> (v & 31)) & 1u);
}

// One warp per batch. Lane L owns states va=(L even?L:L+32) in mA and vb=va^32 in mB.
// Both states share predecessors v0=(2L)%64, v1=(2L+1)%64, delivered by exactly
// TWO shuffles per step via the exposure rule above.
__global__ void __launch_bounds__(128, 1) cva_kernel(const float* __restrict__ x,
                                                     float* __restrict__ out)
{
    extern __shared__ uint32_t snap_smem[];
    const int warp  = threadIdx.x >> 5;
    const int lane  = threadIdx.x & 31;
    const int batch = blockIdx.x * 4 + warp;
    uint32_t* snap = snap_smem + warp * 4096;   // 64 snapshots x 64 states

    const float4* xq = reinterpret_cast<const float4*>(x + (size_t)batch * 2048);

    const bool evn = (lane & 1) == 0;
    const int  va  = evn ? lane : lane + 32;
    const int  vb  = evn ? lane + 32 : lane;
    const bool h   = lane < 16;
    const int idxA = h ? 2 * lane : 2 * lane - 31;
    const int idxB = h ? 2 * lane + 1 : 2 * lane - 32;

    // code bits: c0(s,j)=parity(s&0x3C)^j, c1(s,j)=parity(s&0x2D)^j; state va edge j=0 -> (ea,fa)
    // state vb = va^32 has complementary codes, so only two bm values per lane: bmP, bmQ.
    const float ea = (float)(__popc(va & 0x3C) & 1);
    const float fa = (float)(__popc(va & 0x2D) & 1);
    const float eb = 1.0f - ea, fb = 1.0f - fa;
    const float sgn = h ? 1.0f : -1.0f;

    float    mA = 0.0f, mB = 0.0f;     // path metrics (in_prob0 = 0)
    uint32_t WA = 0u,   WB = 0u;       // 32-bit traceback windows

    // One trellis step. dnA/dnB carry the signed decision discriminants.
    auto acs = [&](float l0, float l1, float& dnA, float& dnB) {
        float bmP = fmaf(l1, fa, l0 * ea);      // bm(va, j=0) == bm(vb, j=1)
        float bmQ = fmaf(l1, fb, l0 * eb);      // bm(va, j=1) == bm(vb, j=0)
        float bmX = h ? bmP : bmQ;              // pairs with xA (lane-const select, off-chain)
        float bmY = h ? bmQ : bmP;              // pairs with xB
        float xA = __shfl_sync(FULLMASK, mA, idxA);   // h: m[v0], else m[v1]
        float xB = __shfl_sync(FULLMASK, mB, idxB);   // h: m[v1], else m[v0]
        float taA = xA + bmX, taB = xB + bmY;         // candidates for state va
        float tbA = xA + bmY, tbB = xB + bmX;         // candidates for state vb
        mA = fmaxf(fminf(fminf(taA, taB), 20.0f), -20.0f);
        mB = fmaxf(fminf(fminf(tbA, tbB), 20.0f), -20.0f);
        dnA = (taB - taA) * sgn;                // j = (dn < 0); ties -> j=0 (matches argmin)
        dnB = (tbB - tbA) * sgn;
    };

    // ---- phase A: t in [0,1024), no decision tracking needed ----
    for (int ch = 0; ch < 32; ++ch) {
        const float4* qp = xq + (ch << 4);
        #pragma unroll 4
        for (int q = 0; q < 16; ++q) {
            float4 v = qp[q];
            float d0, d1;
            acs(v.x, v.y, d0, d1);
            acs(v.z, v.w, d0, d1);
        }
    }

    // ---- phase B: t in [1024,3072), track decisions, snapshot W every 32 steps ----
    for (int ch = 32; ch < 96; ++ch) {
        const float4* qp = xq + ((ch & 31) << 4);
        #pragma unroll
        for (int g = 0; g < 4; ++g) {           // 4 groups of 8 steps
            uint32_t dAm[8], dBm[8];
            #pragma unroll
            for (int q = 0; q < 4; ++q) {
                float4 v = qp[g * 4 + q];
                float dnA, dnB;
                acs(v.x, v.y, dnA, dnB);
                dAm[2 * q]     = __ballot_sync(FULLMASK, dnA < 0.0f);
                dBm[2 * q]     = __ballot_sync(FULLMASK, dnB < 0.0f);
                acs(v.z, v.w, dnA, dnB);
                dAm[2 * q + 1] = __ballot_sync(FULLMASK, dnA < 0.0f);
                dBm[2 * q + 1] = __ballot_sync(FULLMASK, dnB < 0.0f);
            }
            // 8-step W splice: walk own states 8 steps back through the masks,
            // then fetch the 8-steps-ago window of the reached state (4 shuffles / 8 steps).
            uint32_t bitsA = 0; int s = va;
            #pragma unroll
            for (int k = 0; k < 8; ++k) {
                int j = dec_bit(dAm[7 - k], dBm[7 - k], s);
                bitsA |= (uint32_t)j << k;
                s = (2 * s + j) & 63;
            }
            const int sA8 = s;
            uint32_t bitsB = 0; s = vb;
            #pragma unroll
            for (int k = 0; k < 8; ++k) {
                int j = dec_bit(dAm[7 - k], dBm[7 - k], s);
                bitsB |= (uint32_t)j << k;
                s = (2 * s + j) & 63;
            }
            const int sB8 = s;
            uint32_t wAa = __shfl_sync(FULLMASK, WA, sA8 & 31);
            uint32_t wBa = __shfl_sync(FULLMASK, WB, sA8 & 31);
            uint32_t wAb = __shfl_sync(FULLMASK, WA, sB8 & 31);
            uint32_t wBb = __shfl_sync(FULLMASK, WB, sB8 & 31);
            uint32_t woA = (((sA8 >> 5) ^ sA8) & 1) ? wBa : wAa;
            uint32_t woB = (((sB8 >> 5) ^ sB8) & 1) ? wBb : wAb;
            WA = (woA << 8) | bitsA;
            WB = (woB << 8) | bitsB;
        }
        const int c = ch - 32;                   // 0..63
        snap[(c << 6) + va] = WA;                // bank = lane: conflict-free
        snap[(c << 6) + vb] = WB;
    }

    __syncwarp();

    // Traceback: start state 0 at t=3072; one 32-bit window per hop (64 hops).
    float* orow = out + (size_t)batch * 1024;
    int s = 0;
    for (int c = 63; c >= 0; --c) {
        uint32_t w = snap[(c << 6) + s];         // same addr all lanes: LDS broadcast
        if (c <= 32) {
            int idx = (c << 5) + 30 - lane;
            if ((unsigned)idx < 1024u) {
                orow[idx] = ((w >> lane) & 1u) ? 0.0f : 1.0f;
            }
        }
        s = (int)(__brev(w) & 63u);              // state 32 steps earlier
    }
}

extern "C" void kernel_launch(void* const* d_in, const int* in_sizes, int n_in,
                              void* d_out, int out_size)
{
    const float* x = (const float*)d_in[0];
    float* out = (float*)d_out;
    cudaFuncSetAttribute(cva_kernel, cudaFuncAttributeMaxDynamicSharedMemorySize, 65536);
    cva_kernel<<<128, 128, 65536>>>(x, out);
}

// round 3
// speedup vs baseline: 1.0257x; 1.0257x over previous
#include <cuda_runtime.h>
#include <cstdint>

#define FULLMASK 0xffffffffu

// One warp per batch. Lane L owns states (2L, 2L+1) as (mA, mB)  [R1 layout].
// RADIX-4: two trellis steps per shuffle round. For the destination pair
// (2L, 2L+1), the radix-4 ancestors are m[(8L+k)%64], k=0..7, which live in
// lanes (4L)&31 .. (4L)&31+3 (both registers). The intermediate step's
// min+clip is computed locally (exact), so the serial SHFL latency is paid
// once per TWO steps instead of once per step.
__global__ void __launch_bounds__(128, 1) cva_kernel(const float* __restrict__ x,
                                                     float* __restrict__ out)
{
    extern __shared__ uint32_t snap_smem[];
    const int warp  = threadIdx.x >> 5;
    const int lane  = threadIdx.x & 31;
    const int batch = blockIdx.x * 4 + warp;
    uint32_t* snap = snap_smem + warp * 4096;   // 64 snapshots x 64 states

    const float4* xq = reinterpret_cast<const float4*>(x + (size_t)batch * 2048);

    const int sA = 2 * lane;           // state of mA
    const int l4 = (4 * lane) & 31;    // base source lane for ancestor fetch

    // Code-bit parities: c0(s,j)=parity(s&0x3C)^j, c1(s,j)=parity(s&0x2D)^j.
    // Intermediates p=(4L+k)%64: e1=parity((4L)&0x3C) (k-independent),
    // c1 = f1 ^ (k&1) ^ j  (only bit0 of 0x2D is touched by k<=3).
    const int  p0  = (4 * lane) & 63;
    const float e1  = (float)(__popc(p0 & 0x3C) & 1);
    const float f1  = (float)(__popc(p0 & 0x2D) & 1);
    const float e1c = 1.0f - e1, f1c = 1.0f - f1;
    // Finals (dests 2L, 2L+1): e2,f2 for 2L; dest 2L+1 flips only c1 (bit0).
    const float e2  = (float)(__popc(sA & 0x3C) & 1);
    const float f2  = (float)(__popc(sA & 0x2D) & 1);
    const float e2c = 1.0f - e2, f2c = 1.0f - f2;

    float    mA = 0.0f, mB = 0.0f;     // path metrics (in_prob0 = 0)
    uint32_t WA = 0u,   WB = 0u;       // 32-bit traceback windows

    // Two trellis steps: llrs (l0,l1) for step t, (m0,m1) for step t+1.
    // TRACK: also update the traceback windows.
    auto two_step = [&]<bool TRACK>(float l0, float l1, float m0, float m1) {
        // Fetch 8 ancestors g[k] = m[(8L+k)%64]  (l4+3 <= 31, no wrap)
        float g0 = __shfl_sync(FULLMASK, mA, l4);
        float g1 = __shfl_sync(FULLMASK, mB, l4);
        float g2 = __shfl_sync(FULLMASK, mA, l4 + 1);
        float g3 = __shfl_sync(FULLMASK, mB, l4 + 1);
        float g4 = __shfl_sync(FULLMASK, mA, l4 + 2);
        float g5 = __shfl_sync(FULLMASK, mB, l4 + 2);
        float g6 = __shfl_sync(FULLMASK, mA, l4 + 3);
        float g7 = __shfl_sync(FULLMASK, mB, l4 + 3);

        // Step-t branch metrics (exact single-rounding; products by 0/1 exact)
        float a0  = l0 * e1,  a1 = l0 * e1c;
        float b00 = fmaf(l1, f1,  a0);   // (c0,c1)=(e1,f1)   : k even, j=0
        float b01 = fmaf(l1, f1c, a1);   // (~e1,~f1)         : k even, j=1
        float b10 = fmaf(l1, f1c, a0);   // (e1,~f1)          : k odd,  j=0
        float b11 = fmaf(l1, f1,  a1);   // (~e1,f1)          : k odd,  j=1

        // Intermediate states p_k=(4L+k)%64, k=0..3: ACS + clip (exact per-step)
        float c0a = g0 + b00, c0b = g1 + b01;
        float c1a = g2 + b10, c1b = g3 + b11;
        float c2a = g4 + b00, c2b = g5 + b01;
        float c3a = g6 + b10, c3b = g7 + b11;
        float mi0 = fmaxf(fminf(fminf(c0a, c0b), 20.0f), -20.0f);
        float mi1 = fmaxf(fminf(fminf(c1a, c1b), 20.0f), -20.0f);
        float mi2 = fmaxf(fminf(fminf(c2a, c2b), 20.0f), -20.0f);
        float mi3 = fmaxf(fminf(fminf(c3a, c3b), 20.0f), -20.0f);

        // Step-(t+1) branch metrics
        float d0  = m0 * e2,  d1 = m0 * e2c;
        float e00 = fmaf(m1, f2,  d0);   // dest 2L,   j=0
        float e01 = fmaf(m1, f2c, d1);   // dest 2L,   j=1
        float e10 = fmaf(m1, f2c, d0);   // dest 2L+1, j=0
        float e11 = fmaf(m1, f2,  d1);   // dest 2L+1, j=1

        float fa0 = mi0 + e00, fa1 = mi1 + e01;
        float fb0 = mi2 + e10, fb1 = mi3 + e11;
        mA = fmaxf(fminf(fminf(fa0, fa1), 20.0f), -20.0f);
        mB = fmaxf(fminf(fminf(fb0, fb1), 20.0f), -20.0f);

        if constexpr (TRACK) {
            // argmin tie -> j=0 (strict <), matches jnp.argmin
            int ji0 = c0b < c0a, ji1 = c1b < c1a, ji2 = c2b < c2a, ji3 = c3b < c3a;
            int jfA = fa1 < fa0, jfB = fb1 < fb0;
            int jiA = jfA ? ji1 : ji0;       // decision of chosen intermediate
            int jiB = jfB ? ji3 : ji2;
            // W source: state q=(8L+2jf+ji)%64 -> lane (4L+jf)&31 (=l4+jf), reg ji
            uint32_t wa0 = __shfl_sync(FULLMASK, WA, l4 + jfA);
            uint32_t wa1 = __shfl_sync(FULLMASK, WB, l4 + jfA);
            uint32_t wb0 = __shfl_sync(FULLMASK, WA, l4 + 2 + jfB);
            uint32_t wb1 = __shfl_sync(FULLMASK, WB, l4 + 2 + jfB);
            uint32_t wsA = jiA ? wa1 : wa0;
            uint32_t wsB = jiB ? wb1 : wb0;
            WA = (wsA << 2) | ((uint32_t)jiA << 1) | (uint32_t)jfA;
            WB = (wsB << 2) | ((uint32_t)jiB << 1) | (uint32_t)jfB;
        }
    };

    // ---- phase A: t in [0,1024) = 512 two-step groups, no tracking ----
    #pragma unroll 4
    for (int g = 0; g < 512; ++g) {
        float4 v = xq[g];
        two_step.template operator()<false>(v.x, v.y, v.z, v.w);
    }

    // ---- phase B: t in [1024,3072), track + snapshot W every 32 steps ----
    for (int c = 0; c < 64; ++c) {
        #pragma unroll 4
        for (int i = 0; i < 16; ++i) {
            float4 v = xq[(c * 16 + i) & 511];
            two_step.template operator()<true>(v.x, v.y, v.z, v.w);
        }
        *reinterpret_cast<uint2*>(&snap[(c << 6) + sA]) = make_uint2(WA, WB);
    }

    __syncwarp();

    // Traceback: start state 0 at t=3072; one 32-bit window per hop (64 hops).
    float* orow = out + (size_t)batch * 1024;
    int s = 0;
    for (int c = 63; c >= 0; --c) {
        uint32_t w = snap[(c << 6) + s];     // same addr all lanes: LDS broadcast
        if (c <= 32) {
            int idx = (c << 5) + 30 - lane;
            if ((unsigned)idx < 1024u) {
                orow[idx] = ((w >> lane) & 1u) ? 0.0f : 1.0f;
            }
        }
        s = (int)(__brev(w) & 63u);          // state 32 steps earlier
    }
}

extern "C" void kernel_launch(void* const* d_in, const int* in_sizes, int n_in,
                              void* d_out, int out_size)
{
    const float* x = (const float*)d_in[0];
    float* out = (float*)d_out;
    cudaFuncSetAttribute(cva_kernel, cudaFuncAttributeMaxDynamicSharedMemorySize, 65536);
    cva_kernel<<<128, 128, 65536>>>(x, out);
}

// round 4
// speedup vs baseline: 1.5481x; 1.5093x over previous
#include <cuda_runtime.h>
#include <cstdint>

#define FULLMASK 0xffffffffu

// One BLOCK per batch; 4 warps = 4 time-chunks of the tracked region [1024,3072).
// Each warp: 256-step zero-init warmup (metric coalescence via the -20 clip
// floor) + 512 tracked steps, snapshotting 32-bit traceback windows every 32
// steps into block-shared smem. Warp 0 then does the single serial traceback.
// ACS core is the (verified exact) R3 radix-4: lane L owns states (2L, 2L+1),
// two trellis steps per shuffle round.
__global__ void __launch_bounds__(128) cva_kernel(const float* __restrict__ x,
                                                  float* __restrict__ out)
{
    extern __shared__ uint32_t snap[];            // 64 snapshots x 64 states = 16KB
    const int warp  = threadIdx.x >> 5;           // chunk id 0..3
    const int lane  = threadIdx.x & 31;
    const int batch = blockIdx.x;

    const float4* xq = reinterpret_cast<const float4*>(x + (size_t)batch * 2048);

    const int sA = 2 * lane;            // state of mA
    const int l4 = (4 * lane) & 31;     // base source lane for ancestor fetch

    // Code-bit parities: c0(s,j)=parity(s&0x3C)^j, c1(s,j)=parity(s&0x2D)^j.
    const int   p0  = (4 * lane) & 63;
    const float e1  = (float)(__popc(p0 & 0x3C) & 1);
    const float f1  = (float)(__popc(p0 & 0x2D) & 1);
    const float e1c = 1.0f - e1, f1c = 1.0f - f1;
    const float e2  = (float)(__popc(sA & 0x3C) & 1);
    const float f2  = (float)(__popc(sA & 0x2D) & 1);
    const float e2c = 1.0f - e2, f2c = 1.0f - f2;

    float    mA = 0.0f, mB = 0.0f;      // zero-init at chunk warmup start
    uint32_t WA = 0u,   WB = 0u;

    // Two trellis steps (radix-4). TRACK: update traceback windows.
    auto two_step = [&]<bool TRACK>(float l0, float l1, float m0, float m1) {
        float g0 = __shfl_sync(FULLMASK, mA, l4);
        float g1 = __shfl_sync(FULLMASK, mB, l4);
        float g2 = __shfl_sync(FULLMASK, mA, l4 + 1);
        float g3 = __shfl_sync(FULLMASK, mB, l4 + 1);
        float g4 = __shfl_sync(FULLMASK, mA, l4 + 2);
        float g5 = __shfl_sync(FULLMASK, mB, l4 + 2);
        float g6 = __shfl_sync(FULLMASK, mA, l4 + 3);
        float g7 = __shfl_sync(FULLMASK, mB, l4 + 3);

        float a0  = l0 * e1,  a1 = l0 * e1c;
        float b00 = fmaf(l1, f1,  a0);
        float b01 = fmaf(l1, f1c, a1);
        float b10 = fmaf(l1, f1c, a0);
        float b11 = fmaf(l1, f1,  a1);

        float c0a = g0 + b00, c0b = g1 + b01;
        float c1a = g2 + b10, c1b = g3 + b11;
        float c2a = g4 + b00, c2b = g5 + b01;
        float c3a = g6 + b10, c3b = g7 + b11;
        float mi0 = fmaxf(fminf(fminf(c0a, c0b), 20.0f), -20.0f);
        float mi1 = fmaxf(fminf(fminf(c1a, c1b), 20.0f), -20.0f);
        float mi2 = fmaxf(fminf(fminf(c2a, c2b), 20.0f), -20.0f);
        float mi3 = fmaxf(fminf(fminf(c3a, c3b), 20.0f), -20.0f);

        float d0  = m0 * e2,  d1 = m0 * e2c;
        float e00 = fmaf(m1, f2,  d0);
        float e01 = fmaf(m1, f2c, d1);
        float e10 = fmaf(m1, f2c, d0);
        float e11 = fmaf(m1, f2,  d1);

        float fa0 = mi0 + e00, fa1 = mi1 + e01;
        float fb0 = mi2 + e10, fb1 = mi3 + e11;
        mA = fmaxf(fminf(fminf(fa0, fa1), 20.0f), -20.0f);
        mB = fmaxf(fminf(fminf(fb0, fb1), 20.0f), -20.0f);

        if constexpr (TRACK) {
            int ji0 = c0b < c0a, ji1 = c1b < c1a, ji2 = c2b < c2a, ji3 = c3b < c3a;
            int jfA = fa1 < fa0, jfB = fb1 < fb0;
            int jiA = jfA ? ji1 : ji0;
            int jiB = jfB ? ji3 : ji2;
            uint32_t wa0 = __shfl_sync(FULLMASK, WA, l4 + jfA);
            uint32_t wa1 = __shfl_sync(FULLMASK, WB, l4 + jfA);
            uint32_t wb0 = __shfl_sync(FULLMASK, WA, l4 + 2 + jfB);
            uint32_t wb1 = __shfl_sync(FULLMASK, WB, l4 + 2 + jfB);
            uint32_t wsA = jiA ? wa1 : wa0;
            uint32_t wsB = jiB ? wb1 : wb0;
            WA = (wsA << 2) | ((uint32_t)jiA << 1) | (uint32_t)jfA;
            WB = (wsB << 2) | ((uint32_t)jiB << 1) | (uint32_t)jfB;
        }
    };

    // Chunk w: warmup steps [768+512w, 1024+512w), tracked [1024+512w, 1536+512w).
    // float4 group index for step t is (t/2) & 511  (x tiled with period 1024).
    const int g0i = (768 + 512 * warp) >> 1;      // first warmup two-step group

    #pragma unroll 4
    for (int i = 0; i < 128; ++i) {               // 256 warmup steps, untracked
        float4 v = xq[(g0i + i) & 511];
        two_step.template operator()<false>(v.x, v.y, v.z, v.w);
    }

    const int cbase = warp << 4;                  // snapshots 16w .. 16w+15
    for (int c = 0; c < 16; ++c) {
        const int gb = g0i + 128 + (c << 4);
        #pragma unroll 4
        for (int i = 0; i < 16; ++i) {            // 32 tracked steps
            float4 v = xq[(gb + i) & 511];
            two_step.template operator()<true>(v.x, v.y, v.z, v.w);
        }
        *reinterpret_cast<uint2*>(&snap[((cbase + c) << 6) + sA]) =
            make_uint2(WA, WB);
    }

    __syncthreads();

    // Serial traceback over the block-shared table: warp 0 only.
    if (warp == 0) {
        float* orow = out + (size_t)batch * 1024;
        int s = 0;                                 // state 0 at t = 3072
        for (int c = 63; c >= 0; --c) {
            uint32_t w = snap[(c << 6) + s];       // uniform addr: LDS broadcast
            if (c <= 32) {
                int idx = (c << 5) + 30 - lane;
                if ((unsigned)idx < 1024u) {
                    orow[idx] = ((w >> lane) & 1u) ? 0.0f : 1.0f;
                }
            }
            s = (int)(__brev(w) & 63u);            // state 32 steps earlier
        }
    }
}

extern "C" void kernel_launch(void* const* d_in, const int* in_sizes, int n_in,
                              void* d_out, int out_size)
{
    const float* x = (const float*)d_in[0];
    float* out = (float*)d_out;
    cva_kernel<<<512, 128, 16384>>>(x, out);
}